// round 9
// baseline (speedup 1.0000x reference)
#include <cuda_runtime.h>
#include <math.h>

typedef unsigned long long ull;

// Problem constants
static constexpr int B = 64;
static constexpr int T = 512;
static constexpr int I = 1024;
static constexpr int H = 1024;
static constexpr int G4H = 4 * H;   // 4096

static constexpr int NCTA = 128;
static constexpr int NTHR = 512;

// Scratch in device globals (no allocation allowed)
__device__ float g_xproj[(size_t)T * B * G4H];  // [T][B][4H]
__device__ float g_h[2][B * H];                 // h ping-pong
__device__ unsigned g_bar_count = 0;
__device__ unsigned g_bar_sense = 0;

// ---------------------------------------------------------------------------
// f32x2 packed-FMA helpers
// ---------------------------------------------------------------------------
__device__ __forceinline__ ull dup2(float x) {
    ull r; asm("mov.b64 %0, {%1, %1};" : "=l"(r) : "f"(x)); return r;
}
__device__ __forceinline__ void fma2(ull& d, ull a, ull b) {
    asm("fma.rn.f32x2 %0, %1, %2, %0;" : "+l"(d) : "l"(a), "l"(b));
}
__device__ __forceinline__ float2 unpack2(ull v) {
    float2 f; asm("mov.b64 {%0, %1}, %2;" : "=f"(f.x), "=f"(f.y) : "l"(v)); return f;
}
__device__ __forceinline__ ull d2l(double d) { return __double_as_longlong(d); }

__device__ __forceinline__ float fast_tanh(float x) {
    float y; asm("tanh.approx.f32 %0, %1;" : "=f"(y) : "f"(x)); return y;
}
__device__ __forceinline__ float fast_sigmoid(float x) {
    return 0.5f * fast_tanh(0.5f * x) + 0.5f;
}

// ---------------------------------------------------------------------------
// init: zero h[0]
// ---------------------------------------------------------------------------
__global__ void init_kernel() {
    int i = blockIdx.x * blockDim.x + threadIdx.x;
    if (i < B * H) g_h[0][i] = 0.0f;
}

// ---------------------------------------------------------------------------
// xproj GEMM (unchanged): C = x @ Wx + b, scattered to [t][b][4H]
// ---------------------------------------------------------------------------
static constexpr int BM = 128;
static constexpr int BN = 128;
static constexpr int BK = 16;

__device__ __forceinline__ ull dup2x(float x) { return dup2(x); }

__global__ void __launch_bounds__(256) xproj_kernel(
    const float* __restrict__ x,
    const float* __restrict__ w0, const float* __restrict__ w1,
    const float* __restrict__ w2, const float* __restrict__ w3,
    const float* __restrict__ b0, const float* __restrict__ b1,
    const float* __restrict__ b2, const float* __restrict__ b3)
{
    const int tid = threadIdx.x;
    const int m0 = blockIdx.y * BM;
    const int n0 = blockIdx.x * BN;
    const int gate = n0 >> 10;
    const float* __restrict__ w = (gate == 0) ? w0 : (gate == 1) ? w1 : (gate == 2) ? w2 : w3;
    const float* __restrict__ bias = (gate == 0) ? b0 : (gate == 1) ? b1 : (gate == 2) ? b2 : b3;
    const int j0 = n0 & (H - 1);

    __shared__ float As[BK][BM + 4];
    __shared__ float Bs[BK][BN + 4];

    const int tx = tid & 15;
    const int ty = tid >> 4;

    ull acc[4][8];
    #pragma unroll
    for (int i = 0; i < 4; ++i)
        #pragma unroll
        for (int j = 0; j < 8; ++j) acc[i][j] = 0ULL;

    const int ar = tid >> 2;
    const int ak = (tid & 3) * 4;
    const int bk = tid >> 5;
    const int bc = (tid & 31) * 4;

    for (int k0 = 0; k0 < I; k0 += BK) {
        #pragma unroll
        for (int p = 0; p < 2; ++p) {
            int r = ar + p * 64;
            float4 v = *reinterpret_cast<const float4*>(&x[(size_t)(m0 + r) * I + k0 + ak]);
            As[ak + 0][r] = v.x;
            As[ak + 1][r] = v.y;
            As[ak + 2][r] = v.z;
            As[ak + 3][r] = v.w;
        }
        #pragma unroll
        for (int p = 0; p < 2; ++p) {
            int kk = bk + p * 8;
            float4 v = *reinterpret_cast<const float4*>(&w[(size_t)(k0 + kk) * H + j0 + bc]);
            *reinterpret_cast<float4*>(&Bs[kk][bc]) = v;
        }
        __syncthreads();

        #pragma unroll
        for (int kk = 0; kk < BK; ++kk) {
            double2 da = *reinterpret_cast<const double2*>(&As[kk][ty * 8]);
            double2 db = *reinterpret_cast<const double2*>(&As[kk][ty * 8 + 4]);
            ull arw[4] = {d2l(da.x), d2l(da.y), d2l(db.x), d2l(db.y)};
            float4 c0 = *reinterpret_cast<const float4*>(&Bs[kk][tx * 8]);
            float4 c1 = *reinterpret_cast<const float4*>(&Bs[kk][tx * 8 + 4]);
            float bf_[8] = {c0.x, c0.y, c0.z, c0.w, c1.x, c1.y, c1.z, c1.w};
            #pragma unroll
            for (int j = 0; j < 8; ++j) {
                ull bj = dup2x(bf_[j]);
                #pragma unroll
                for (int i = 0; i < 4; ++i)
                    fma2(acc[i][j], arw[i], bj);
            }
        }
        __syncthreads();
    }

    #pragma unroll
    for (int i2 = 0; i2 < 4; ++i2) {
        #pragma unroll
        for (int half = 0; half < 2; ++half) {
            int m = m0 + ty * 8 + i2 * 2 + half;
            int t = m & (T - 1);
            int bi_ = m >> 9;
            size_t base = ((size_t)t * B + bi_) * G4H + n0;
            #pragma unroll
            for (int j = 0; j < 8; ++j) {
                float2 u = unpack2(acc[i2][j]);
                float v = half ? u.y : u.x;
                int n = tx * 8 + j;
                g_xproj[base + n] = v + bias[j0 + n];
            }
        }
    }
}

// ---------------------------------------------------------------------------
// Persistent LSTM recurrence v3 — broadcast-weight layout (crossbar-lean).
//
// 128 CTAs x 512 threads (16 warps), 1 CTA/SM. CTA cg owns 32 fused cols
// (fc = gate*8 + jj, jj in [0,8) mapping to H-col j0+jj), all 64 rows.
//
// Warp w: fcq = w&3 (8 fc: [fcq*8, fcq*8+8)), kq = w>>2 (k-split 4,
// interleaved 32-k blocks: k-block kb belongs to kq = kb%4).
// Lane l covers rows {l, l+32}. Per k:
//   w operands: ws[k][fcq*8..+8] as 4 f32x2 — LDS.128 x2, BROADCAST (all
//   lanes same address -> ~16B unique per request instead of 512B).
//   h operands: hs[row][k] (untransposed!) — LDS.128 covers 4 k per row;
//   dup2 per (row,k) on ALU pipe.
//   8 FFMA2 (2 rows x 4 fc-pairs).
// Crossbar bytes/MAC ~0.3 (was 2.5) -> smem no longer binding; FMA floor
// 16,384 cyc/step governs.
//
// SMEM: ws [1024][32] f32 (128KB, loaded once)
//       hs [2][64][132] f32 (67.5KB, double-buffered 128-k chunks; staging is
//                            straight LDG.128->STS.128, no transpose)
//       gt [64][36] f32 (9KB)
// ---------------------------------------------------------------------------
static constexpr int KCH = 128;                  // k chunk
static constexpr int NCH = H / KCH;              // 8
static constexpr int HROW = 132;                 // 128 + 4 pad
static constexpr int WS_FLOATS = H * 32;                 // 32768
static constexpr int HS_FLOATS = 2 * 64 * HROW;          // 16896
static constexpr int GT_STRIDE = 36;
static constexpr int GT_FLOATS = 64 * GT_STRIDE;         // 2304
static constexpr size_t SMEM_BYTES =
    (size_t)(WS_FLOATS + HS_FLOATS + GT_FLOATS) * 4;     // 207,872

__global__ void __launch_bounds__(NTHR, 1) lstm_persistent(
    const float* __restrict__ wh0, const float* __restrict__ wh1,
    const float* __restrict__ wh2, const float* __restrict__ wh3,
    float* __restrict__ out)
{
    extern __shared__ float smem[];
    float* ws = smem;                            // [1024][32]
    float* hs = smem + WS_FLOATS;                // [2][64][HROW]
    float* gt = smem + WS_FLOATS + HS_FLOATS;    // [64][36]
    __shared__ unsigned s_sense;

    const int tid  = threadIdx.x;
    const int cg   = blockIdx.x;
    const int j0   = cg * 8;
    const int lane = tid & 31;
    const int wrp  = tid >> 5;
    const int fcq  = wrp & 3;                    // fc quad
    const int kq   = wrp >> 2;                   // k split index

    // ---- load Wh slice into ws once: ws[k][fc] ----
    for (int idx = tid; idx < 1024 * 8; idx += NTHR) {
        int kk = idx >> 3;
        int q = idx & 7;                         // fc quad-of-4: fc = q*4..
        int gate = q >> 1;
        int jj4 = (q & 1) * 4;
        const float* __restrict__ wsel = (gate == 0) ? wh0 : (gate == 1) ? wh1
                                       : (gate == 2) ? wh2 : wh3;
        float4 v = *reinterpret_cast<const float4*>(&wsel[(size_t)kk * H + j0 + jj4]);
        *reinterpret_cast<float4*>(&ws[kk * 32 + q * 4]) = v;
    }
    if (tid == 0) s_sense = 0;
    __syncthreads();

    // pointwise ownership
    const int prow = tid >> 3;
    const int pjj = tid & 7;
    float creg = 0.0f;

    // staging mapping: 4 float4 per thread per chunk
    // idx = tid + 512*j ; row = idx>>5 ; k4 = idx&31
    for (int t = 0; t < T; ++t) {
        const float* __restrict__ hin = g_h[t & 1];
        float* __restrict__ hout = g_h[(t + 1) & 1];

        // xproj prefetch: kq==0 warps own the first gt pass
        float4 xpa[2], xpb[2];
        if (kq == 0) {
            #pragma unroll
            for (int rs = 0; rs < 2; ++rs) {
                int row = lane + rs * 32;
                size_t base = ((size_t)t * B + row) * G4H + (size_t)fcq * H + j0;
                xpa[rs] = *reinterpret_cast<const float4*>(&g_xproj[base]);
                xpb[rs] = *reinterpret_cast<const float4*>(&g_xproj[base + 4]);
            }
        }

        // stage chunk 0
        #pragma unroll
        for (int jld = 0; jld < 4; ++jld) {
            int idx = tid + 512 * jld;
            int row = idx >> 5;
            int k4 = idx & 31;
            float4 v = __ldcg(reinterpret_cast<const float4*>(&hin[row * H + k4 * 4]));
            *reinterpret_cast<float4*>(&hs[row * HROW + k4 * 4]) = v;
        }
        __syncthreads();

        ull acc[2][4];
        #pragma unroll
        for (int r = 0; r < 2; ++r)
            #pragma unroll
            for (int p = 0; p < 4; ++p) acc[r][p] = 0ULL;

        for (int c = 0; c < NCH; ++c) {
            // register-prefetch chunk c+1
            float4 pf[4];
            if (c + 1 < NCH) {
                #pragma unroll
                for (int jld = 0; jld < 4; ++jld) {
                    int idx = tid + 512 * jld;
                    int row = idx >> 5;
                    int k4 = idx & 31;
                    pf[jld] = __ldcg(reinterpret_cast<const float4*>(
                        &hin[row * H + (c + 1) * KCH + k4 * 4]));
                }
            }

            // compute this warp's 32-k window of the chunk
            const float* hb = hs + (c & 1) * (64 * HROW);
            const float* hap = hb + lane * HROW + kq * 32;
            const float* hbp = hb + (lane + 32) * HROW + kq * 32;
            const float* wsb = ws + (size_t)(c * KCH + kq * 32) * 32 + fcq * 8;

            #pragma unroll
            for (int k4 = 0; k4 < 8; ++k4) {
                float4 ha = *reinterpret_cast<const float4*>(hap + k4 * 4);
                float4 hbv = *reinterpret_cast<const float4*>(hbp + k4 * 4);
                const float* wk = wsb + k4 * 4 * 32;
                #pragma unroll
                for (int i = 0; i < 4; ++i) {
                    longlong2 w01 = *reinterpret_cast<const longlong2*>(wk + i * 32);
                    longlong2 w23 = *reinterpret_cast<const longlong2*>(wk + i * 32 + 4);
                    ull a0 = dup2((&ha.x)[i]);
                    ull a1 = dup2((&hbv.x)[i]);
                    fma2(acc[0][0], a0, (ull)w01.x);
                    fma2(acc[0][1], a0, (ull)w01.y);
                    fma2(acc[0][2], a0, (ull)w23.x);
                    fma2(acc[0][3], a0, (ull)w23.y);
                    fma2(acc[1][0], a1, (ull)w01.x);
                    fma2(acc[1][1], a1, (ull)w01.y);
                    fma2(acc[1][2], a1, (ull)w23.x);
                    fma2(acc[1][3], a1, (ull)w23.y);
                }
            }

            // commit prefetched chunk
            if (c + 1 < NCH) {
                float* hn = hs + ((c + 1) & 1) * (64 * HROW);
                #pragma unroll
                for (int jld = 0; jld < 4; ++jld) {
                    int idx = tid + 512 * jld;
                    int row = idx >> 5;
                    int k4 = idx & 31;
                    *reinterpret_cast<float4*>(&hn[row * HROW + k4 * 4]) = pf[jld];
                }
            }
            __syncthreads();
        }

        // ---- k-split(4) reduction into gt: pass p handled by kq==p warps ----
        #pragma unroll
        for (int p = 0; p < 4; ++p) {
            if (kq == p) {
                #pragma unroll
                for (int rs = 0; rs < 2; ++rs) {
                    int row = lane + rs * 32;
                    float* g = gt + row * GT_STRIDE + fcq * 8;
                    float2 u0 = unpack2(acc[rs][0]);
                    float2 u1 = unpack2(acc[rs][1]);
                    float2 u2 = unpack2(acc[rs][2]);
                    float2 u3 = unpack2(acc[rs][3]);
                    if (p == 0) {
                        float4 va = make_float4(u0.x + xpa[rs].x, u0.y + xpa[rs].y,
                                                u1.x + xpa[rs].z, u1.y + xpa[rs].w);
                        float4 vb = make_float4(u2.x + xpb[rs].x, u2.y + xpb[rs].y,
                                                u3.x + xpb[rs].z, u3.y + xpb[rs].w);
                        *reinterpret_cast<float4*>(g) = va;
                        *reinterpret_cast<float4*>(g + 4) = vb;
                    } else {
                        float4 va = *reinterpret_cast<const float4*>(g);
                        float4 vb = *reinterpret_cast<const float4*>(g + 4);
                        va.x += u0.x; va.y += u0.y; va.z += u1.x; va.w += u1.y;
                        vb.x += u2.x; vb.y += u2.y; vb.z += u3.x; vb.w += u3.y;
                        *reinterpret_cast<float4*>(g) = va;
                        *reinterpret_cast<float4*>(g + 4) = vb;
                    }
                }
            }
            __syncthreads();
        }

        // ---- pointwise LSTM cell: one element per thread ----
        {
            float gi = gt[prow * GT_STRIDE + 0 + pjj];
            float gf = gt[prow * GT_STRIDE + 8 + pjj];
            float gg = gt[prow * GT_STRIDE + 16 + pjj];
            float go = gt[prow * GT_STRIDE + 24 + pjj];
            float ig = fast_sigmoid(gi);
            float fg = fast_sigmoid(gf);
            float gv = fast_tanh(gg);
            float og = fast_sigmoid(go);
            creg = fg * creg + ig * gv;
            float hv = og * fast_tanh(creg);
            int j = j0 + pjj;
            hout[prow * H + j] = hv;
            out[((size_t)prow * T + t) * H + j] = hv;
            if (t == T - 1) {
                size_t off = (size_t)B * T * H;
                out[off + (size_t)prow * H + j] = hv;
                out[off + (size_t)B * H + (size_t)prow * H + j] = creg;
            }
        }

        // ---- grid barrier ----
        __syncthreads();
        if (tid == 0) {
            __threadfence();
            unsigned s = s_sense ^ 1u;
            s_sense = s;
            if (atomicAdd(&g_bar_count, 1u) == NCTA - 1u) {
                g_bar_count = 0;
                asm volatile("st.release.gpu.global.u32 [%0], %1;"
                             :: "l"(&g_bar_sense), "r"(s) : "memory");
            } else {
                unsigned v;
                while (true) {
                    asm volatile("ld.acquire.gpu.global.u32 %0, [%1];"
                                 : "=r"(v) : "l"(&g_bar_sense) : "memory");
                    if (v == s) break;
                    __nanosleep(32);
                }
            }
        }
        __syncthreads();
    }
}

// ---------------------------------------------------------------------------
extern "C" void kernel_launch(void* const* d_in, const int* in_sizes, int n_in,
                              void* d_out, int out_size)
{
    const float* x   = (const float*)d_in[0];
    const float* wii = (const float*)d_in[1];
    const float* whi = (const float*)d_in[2];
    const float* bi  = (const float*)d_in[3];
    const float* wif = (const float*)d_in[4];
    const float* whf = (const float*)d_in[5];
    const float* bf  = (const float*)d_in[6];
    const float* wig = (const float*)d_in[7];
    const float* whg = (const float*)d_in[8];
    const float* bg  = (const float*)d_in[9];
    const float* wio = (const float*)d_in[10];
    const float* who = (const float*)d_in[11];
    const float* bo  = (const float*)d_in[12];
    float* out = (float*)d_out;

    cudaFuncSetAttribute(lstm_persistent,
                         cudaFuncAttributeMaxDynamicSharedMemorySize,
                         (int)SMEM_BYTES);

    init_kernel<<<(B * H + 255) / 256, 256>>>();

    dim3 gx(G4H / BN, (B * T) / BM);   // (32, 256)
    xproj_kernel<<<gx, 256>>>(x, wii, wif, wig, wio, bi, bf, bg, bo);

    lstm_persistent<<<NCTA, NTHR, SMEM_BYTES>>>(whi, whf, whg, who, out);
}

// round 10
// speedup vs baseline: 1.0032x; 1.0032x over previous
#include <cuda_runtime.h>
#include <math.h>

typedef unsigned long long ull;

// Problem constants
static constexpr int B = 64;
static constexpr int T = 512;
static constexpr int I = 1024;
static constexpr int H = 1024;
static constexpr int G4H = 4 * H;   // 4096

static constexpr int NCTA = 128;
static constexpr int NTHR = 512;

// Scratch in device globals (no allocation allowed)
__device__ float g_xproj[(size_t)T * B * G4H];  // [T][B][4H]
__device__ float g_h[2][B * H];                 // h ping-pong
__device__ unsigned g_bar_count = 0;
__device__ unsigned g_bar_sense = 0;

// ---------------------------------------------------------------------------
// f32x2 packed-FMA helpers
// ---------------------------------------------------------------------------
__device__ __forceinline__ ull dup2(float x) {
    ull r; asm("mov.b64 %0, {%1, %1};" : "=l"(r) : "f"(x)); return r;
}
__device__ __forceinline__ void fma2(ull& d, ull a, ull b) {
    asm("fma.rn.f32x2 %0, %1, %2, %0;" : "+l"(d) : "l"(a), "l"(b));
}
__device__ __forceinline__ float2 unpack2(ull v) {
    float2 f; asm("mov.b64 {%0, %1}, %2;" : "=f"(f.x), "=f"(f.y) : "l"(v)); return f;
}
__device__ __forceinline__ ull d2l(double d) { return __double_as_longlong(d); }

__device__ __forceinline__ float fast_tanh(float x) {
    float y; asm("tanh.approx.f32 %0, %1;" : "=f"(y) : "f"(x)); return y;
}
__device__ __forceinline__ float fast_sigmoid(float x) {
    return 0.5f * fast_tanh(0.5f * x) + 0.5f;
}

// ---------------------------------------------------------------------------
// init: zero h[0]
// ---------------------------------------------------------------------------
__global__ void init_kernel() {
    int i = blockIdx.x * blockDim.x + threadIdx.x;
    if (i < B * H) g_h[0][i] = 0.0f;
}

// ---------------------------------------------------------------------------
// xproj GEMM (unchanged): C = x @ Wx + b, scattered to [t][b][4H]
// ---------------------------------------------------------------------------
static constexpr int BM = 128;
static constexpr int BN = 128;
static constexpr int BK = 16;

__device__ __forceinline__ ull dup2x(float x) { return dup2(x); }

__global__ void __launch_bounds__(256) xproj_kernel(
    const float* __restrict__ x,
    const float* __restrict__ w0, const float* __restrict__ w1,
    const float* __restrict__ w2, const float* __restrict__ w3,
    const float* __restrict__ b0, const float* __restrict__ b1,
    const float* __restrict__ b2, const float* __restrict__ b3)
{
    const int tid = threadIdx.x;
    const int m0 = blockIdx.y * BM;
    const int n0 = blockIdx.x * BN;
    const int gate = n0 >> 10;
    const float* __restrict__ w = (gate == 0) ? w0 : (gate == 1) ? w1 : (gate == 2) ? w2 : w3;
    const float* __restrict__ bias = (gate == 0) ? b0 : (gate == 1) ? b1 : (gate == 2) ? b2 : b3;
    const int j0 = n0 & (H - 1);

    __shared__ float As[BK][BM + 4];
    __shared__ float Bs[BK][BN + 4];

    const int tx = tid & 15;
    const int ty = tid >> 4;

    ull acc[4][8];
    #pragma unroll
    for (int i = 0; i < 4; ++i)
        #pragma unroll
        for (int j = 0; j < 8; ++j) acc[i][j] = 0ULL;

    const int ar = tid >> 2;
    const int ak = (tid & 3) * 4;
    const int bk = tid >> 5;
    const int bc = (tid & 31) * 4;

    for (int k0 = 0; k0 < I; k0 += BK) {
        #pragma unroll
        for (int p = 0; p < 2; ++p) {
            int r = ar + p * 64;
            float4 v = *reinterpret_cast<const float4*>(&x[(size_t)(m0 + r) * I + k0 + ak]);
            As[ak + 0][r] = v.x;
            As[ak + 1][r] = v.y;
            As[ak + 2][r] = v.z;
            As[ak + 3][r] = v.w;
        }
        #pragma unroll
        for (int p = 0; p < 2; ++p) {
            int kk = bk + p * 8;
            float4 v = *reinterpret_cast<const float4*>(&w[(size_t)(k0 + kk) * H + j0 + bc]);
            *reinterpret_cast<float4*>(&Bs[kk][bc]) = v;
        }
        __syncthreads();

        #pragma unroll
        for (int kk = 0; kk < BK; ++kk) {
            double2 da = *reinterpret_cast<const double2*>(&As[kk][ty * 8]);
            double2 db = *reinterpret_cast<const double2*>(&As[kk][ty * 8 + 4]);
            ull arw[4] = {d2l(da.x), d2l(da.y), d2l(db.x), d2l(db.y)};
            float4 c0 = *reinterpret_cast<const float4*>(&Bs[kk][tx * 8]);
            float4 c1 = *reinterpret_cast<const float4*>(&Bs[kk][tx * 8 + 4]);
            float bf_[8] = {c0.x, c0.y, c0.z, c0.w, c1.x, c1.y, c1.z, c1.w};
            #pragma unroll
            for (int j = 0; j < 8; ++j) {
                ull bj = dup2x(bf_[j]);
                #pragma unroll
                for (int i = 0; i < 4; ++i)
                    fma2(acc[i][j], arw[i], bj);
            }
        }
        __syncthreads();
    }

    #pragma unroll
    for (int i2 = 0; i2 < 4; ++i2) {
        #pragma unroll
        for (int half = 0; half < 2; ++half) {
            int m = m0 + ty * 8 + i2 * 2 + half;
            int t = m & (T - 1);
            int bi_ = m >> 9;
            size_t base = ((size_t)t * B + bi_) * G4H + n0;
            #pragma unroll
            for (int j = 0; j < 8; ++j) {
                float2 u = unpack2(acc[i2][j]);
                float v = half ? u.y : u.x;
                int n = tx * 8 + j;
                g_xproj[base + n] = v + bias[j0 + n];
            }
        }
    }
}

// ---------------------------------------------------------------------------
// Persistent LSTM recurrence v3 — broadcast-weight layout (crossbar-lean).
//
// 128 CTAs x 512 threads (16 warps), 1 CTA/SM. CTA cg owns 32 fused cols
// (fc = gate*8 + jj, jj in [0,8) mapping to H-col j0+jj), all 64 rows.
//
// Warp w: fcq = w&3 (8 fc: [fcq*8, fcq*8+8)), kq = w>>2 (k-split 4,
// interleaved 32-k blocks: k-block kb belongs to kq = kb%4).
// Lane l covers rows {l, l+32}. Per k:
//   w operands: ws[k][fcq*8..+8] as 4 f32x2 — LDS.128 x2, BROADCAST (all
//   lanes same address -> ~16B unique per request instead of 512B).
//   h operands: hs[row][k] (untransposed!) — LDS.128 covers 4 k per row;
//   dup2 per (row,k) on ALU pipe.
//   8 FFMA2 (2 rows x 4 fc-pairs).
// Crossbar bytes/MAC ~0.3 (was 2.5) -> smem no longer binding; FMA floor
// 16,384 cyc/step governs.
//
// SMEM: ws [1024][32] f32 (128KB, loaded once)
//       hs [2][64][132] f32 (67.5KB, double-buffered 128-k chunks; staging is
//                            straight LDG.128->STS.128, no transpose)
//       gt [64][36] f32 (9KB)
// ---------------------------------------------------------------------------
static constexpr int KCH = 128;                  // k chunk
static constexpr int NCH = H / KCH;              // 8
static constexpr int HROW = 132;                 // 128 + 4 pad
static constexpr int WS_FLOATS = H * 32;                 // 32768
static constexpr int HS_FLOATS = 2 * 64 * HROW;          // 16896
static constexpr int GT_STRIDE = 36;
static constexpr int GT_FLOATS = 64 * GT_STRIDE;         // 2304
static constexpr size_t SMEM_BYTES =
    (size_t)(WS_FLOATS + HS_FLOATS + GT_FLOATS) * 4;     // 207,872

__global__ void __launch_bounds__(NTHR, 1) lstm_persistent(
    const float* __restrict__ wh0, const float* __restrict__ wh1,
    const float* __restrict__ wh2, const float* __restrict__ wh3,
    float* __restrict__ out)
{
    extern __shared__ float smem[];
    float* ws = smem;                            // [1024][32]
    float* hs = smem + WS_FLOATS;                // [2][64][HROW]
    float* gt = smem + WS_FLOATS + HS_FLOATS;    // [64][36]
    __shared__ unsigned s_sense;

    const int tid  = threadIdx.x;
    const int cg   = blockIdx.x;
    const int j0   = cg * 8;
    const int lane = tid & 31;
    const int wrp  = tid >> 5;
    const int fcq  = wrp & 3;                    // fc quad
    const int kq   = wrp >> 2;                   // k split index

    // ---- load Wh slice into ws once: ws[k][fc] ----
    for (int idx = tid; idx < 1024 * 8; idx += NTHR) {
        int kk = idx >> 3;
        int q = idx & 7;                         // fc quad-of-4: fc = q*4..
        int gate = q >> 1;
        int jj4 = (q & 1) * 4;
        const float* __restrict__ wsel = (gate == 0) ? wh0 : (gate == 1) ? wh1
                                       : (gate == 2) ? wh2 : wh3;
        float4 v = *reinterpret_cast<const float4*>(&wsel[(size_t)kk * H + j0 + jj4]);
        *reinterpret_cast<float4*>(&ws[kk * 32 + q * 4]) = v;
    }
    if (tid == 0) s_sense = 0;
    __syncthreads();

    // pointwise ownership
    const int prow = tid >> 3;
    const int pjj = tid & 7;
    float creg = 0.0f;

    // staging mapping: 4 float4 per thread per chunk
    // idx = tid + 512*j ; row = idx>>5 ; k4 = idx&31
    for (int t = 0; t < T; ++t) {
        const float* __restrict__ hin = g_h[t & 1];
        float* __restrict__ hout = g_h[(t + 1) & 1];

        // xproj prefetch: kq==0 warps own the first gt pass
        float4 xpa[2], xpb[2];
        if (kq == 0) {
            #pragma unroll
            for (int rs = 0; rs < 2; ++rs) {
                int row = lane + rs * 32;
                size_t base = ((size_t)t * B + row) * G4H + (size_t)fcq * H + j0;
                xpa[rs] = *reinterpret_cast<const float4*>(&g_xproj[base]);
                xpb[rs] = *reinterpret_cast<const float4*>(&g_xproj[base + 4]);
            }
        }

        // stage chunk 0
        #pragma unroll
        for (int jld = 0; jld < 4; ++jld) {
            int idx = tid + 512 * jld;
            int row = idx >> 5;
            int k4 = idx & 31;
            float4 v = __ldcg(reinterpret_cast<const float4*>(&hin[row * H + k4 * 4]));
            *reinterpret_cast<float4*>(&hs[row * HROW + k4 * 4]) = v;
        }
        __syncthreads();

        ull acc[2][4];
        #pragma unroll
        for (int r = 0; r < 2; ++r)
            #pragma unroll
            for (int p = 0; p < 4; ++p) acc[r][p] = 0ULL;

        for (int c = 0; c < NCH; ++c) {
            // register-prefetch chunk c+1
            float4 pf[4];
            if (c + 1 < NCH) {
                #pragma unroll
                for (int jld = 0; jld < 4; ++jld) {
                    int idx = tid + 512 * jld;
                    int row = idx >> 5;
                    int k4 = idx & 31;
                    pf[jld] = __ldcg(reinterpret_cast<const float4*>(
                        &hin[row * H + (c + 1) * KCH + k4 * 4]));
                }
            }

            // compute this warp's 32-k window of the chunk
            const float* hb = hs + (c & 1) * (64 * HROW);
            const float* hap = hb + lane * HROW + kq * 32;
            const float* hbp = hb + (lane + 32) * HROW + kq * 32;
            const float* wsb = ws + (size_t)(c * KCH + kq * 32) * 32 + fcq * 8;

            #pragma unroll
            for (int k4 = 0; k4 < 8; ++k4) {
                float4 ha = *reinterpret_cast<const float4*>(hap + k4 * 4);
                float4 hbv = *reinterpret_cast<const float4*>(hbp + k4 * 4);
                const float* wk = wsb + k4 * 4 * 32;
                #pragma unroll
                for (int i = 0; i < 4; ++i) {
                    longlong2 w01 = *reinterpret_cast<const longlong2*>(wk + i * 32);
                    longlong2 w23 = *reinterpret_cast<const longlong2*>(wk + i * 32 + 4);
                    ull a0 = dup2((&ha.x)[i]);
                    ull a1 = dup2((&hbv.x)[i]);
                    fma2(acc[0][0], a0, (ull)w01.x);
                    fma2(acc[0][1], a0, (ull)w01.y);
                    fma2(acc[0][2], a0, (ull)w23.x);
                    fma2(acc[0][3], a0, (ull)w23.y);
                    fma2(acc[1][0], a1, (ull)w01.x);
                    fma2(acc[1][1], a1, (ull)w01.y);
                    fma2(acc[1][2], a1, (ull)w23.x);
                    fma2(acc[1][3], a1, (ull)w23.y);
                }
            }

            // commit prefetched chunk
            if (c + 1 < NCH) {
                float* hn = hs + ((c + 1) & 1) * (64 * HROW);
                #pragma unroll
                for (int jld = 0; jld < 4; ++jld) {
                    int idx = tid + 512 * jld;
                    int row = idx >> 5;
                    int k4 = idx & 31;
                    *reinterpret_cast<float4*>(&hn[row * HROW + k4 * 4]) = pf[jld];
                }
            }
            __syncthreads();
        }

        // ---- k-split(4) reduction into gt: pass p handled by kq==p warps ----
        #pragma unroll
        for (int p = 0; p < 4; ++p) {
            if (kq == p) {
                #pragma unroll
                for (int rs = 0; rs < 2; ++rs) {
                    int row = lane + rs * 32;
                    float* g = gt + row * GT_STRIDE + fcq * 8;
                    float2 u0 = unpack2(acc[rs][0]);
                    float2 u1 = unpack2(acc[rs][1]);
                    float2 u2 = unpack2(acc[rs][2]);
                    float2 u3 = unpack2(acc[rs][3]);
                    if (p == 0) {
                        float4 va = make_float4(u0.x + xpa[rs].x, u0.y + xpa[rs].y,
                                                u1.x + xpa[rs].z, u1.y + xpa[rs].w);
                        float4 vb = make_float4(u2.x + xpb[rs].x, u2.y + xpb[rs].y,
                                                u3.x + xpb[rs].z, u3.y + xpb[rs].w);
                        *reinterpret_cast<float4*>(g) = va;
                        *reinterpret_cast<float4*>(g + 4) = vb;
                    } else {
                        float4 va = *reinterpret_cast<const float4*>(g);
                        float4 vb = *reinterpret_cast<const float4*>(g + 4);
                        va.x += u0.x; va.y += u0.y; va.z += u1.x; va.w += u1.y;
                        vb.x += u2.x; vb.y += u2.y; vb.z += u3.x; vb.w += u3.y;
                        *reinterpret_cast<float4*>(g) = va;
                        *reinterpret_cast<float4*>(g + 4) = vb;
                    }
                }
            }
            __syncthreads();
        }

        // ---- pointwise LSTM cell: one element per thread ----
        {
            float gi = gt[prow * GT_STRIDE + 0 + pjj];
            float gf = gt[prow * GT_STRIDE + 8 + pjj];
            float gg = gt[prow * GT_STRIDE + 16 + pjj];
            float go = gt[prow * GT_STRIDE + 24 + pjj];
            float ig = fast_sigmoid(gi);
            float fg = fast_sigmoid(gf);
            float gv = fast_tanh(gg);
            float og = fast_sigmoid(go);
            creg = fg * creg + ig * gv;
            float hv = og * fast_tanh(creg);
            int j = j0 + pjj;
            hout[prow * H + j] = hv;
            out[((size_t)prow * T + t) * H + j] = hv;
            if (t == T - 1) {
                size_t off = (size_t)B * T * H;
                out[off + (size_t)prow * H + j] = hv;
                out[off + (size_t)B * H + (size_t)prow * H + j] = creg;
            }
        }

        // ---- grid barrier ----
        __syncthreads();
        if (tid == 0) {
            __threadfence();
            unsigned s = s_sense ^ 1u;
            s_sense = s;
            if (atomicAdd(&g_bar_count, 1u) == NCTA - 1u) {
                g_bar_count = 0;
                asm volatile("st.release.gpu.global.u32 [%0], %1;"
                             :: "l"(&g_bar_sense), "r"(s) : "memory");
            } else {
                unsigned v;
                while (true) {
                    asm volatile("ld.acquire.gpu.global.u32 %0, [%1];"
                                 : "=r"(v) : "l"(&g_bar_sense) : "memory");
                    if (v == s) break;
                    __nanosleep(32);
                }
            }
        }
        __syncthreads();
    }
}

// ---------------------------------------------------------------------------
extern "C" void kernel_launch(void* const* d_in, const int* in_sizes, int n_in,
                              void* d_out, int out_size)
{
    const float* x   = (const float*)d_in[0];
    const float* wii = (const float*)d_in[1];
    const float* whi = (const float*)d_in[2];
    const float* bi  = (const float*)d_in[3];
    const float* wif = (const float*)d_in[4];
    const float* whf = (const float*)d_in[5];
    const float* bf  = (const float*)d_in[6];
    const float* wig = (const float*)d_in[7];
    const float* whg = (const float*)d_in[8];
    const float* bg  = (const float*)d_in[9];
    const float* wio = (const float*)d_in[10];
    const float* who = (const float*)d_in[11];
    const float* bo  = (const float*)d_in[12];
    float* out = (float*)d_out;

    cudaFuncSetAttribute(lstm_persistent,
                         cudaFuncAttributeMaxDynamicSharedMemorySize,
                         (int)SMEM_BYTES);

    init_kernel<<<(B * H + 255) / 256, 256>>>();

    dim3 gx(G4H / BN, (B * T) / BM);   // (32, 256)
    xproj_kernel<<<gx, 256>>>(x, wii, wif, wig, wio, bi, bf, bg, bo);

    lstm_persistent<<<NCTA, NTHR, SMEM_BYTES>>>(whi, whf, whg, who, out);
}

// round 12
// speedup vs baseline: 1.3347x; 1.3305x over previous
#include <cuda_runtime.h>
#include <cuda_bf16.h>
#include <math.h>
#include <stdint.h>

typedef unsigned long long ull;

// Problem constants
static constexpr int B = 64;
static constexpr int T = 512;
static constexpr int I = 1024;
static constexpr int H = 1024;
static constexpr int G4H = 4 * H;   // 4096

static constexpr int NCTA = 128;
static constexpr int NTHR = 512;

// Scratch in device globals (no allocation allowed)
__device__ float g_xproj[(size_t)T * B * G4H];  // [T][B][4H]
__device__ float g_h[2][B * H];                 // h ping-pong
__device__ unsigned g_bar_count = 0;
__device__ unsigned g_bar_sense = 0;

// bf16 hi/lo operands for the tensor-core xproj GEMM
__device__ __nv_bfloat16 g_xb_hi[(size_t)B * T * I];   // [m][k]
__device__ __nv_bfloat16 g_xb_lo[(size_t)B * T * I];
__device__ __nv_bfloat16 g_wb_hi[(size_t)G4H * I];     // [fused n][k]  (W^T)
__device__ __nv_bfloat16 g_wb_lo[(size_t)G4H * I];

// ---------------------------------------------------------------------------
// helpers
// ---------------------------------------------------------------------------
__device__ __forceinline__ ull dup2(float x) {
    ull r; asm("mov.b64 %0, {%1, %1};" : "=l"(r) : "f"(x)); return r;
}
__device__ __forceinline__ void fma2(ull& d, ull a, ull b) {
    asm("fma.rn.f32x2 %0, %1, %2, %0;" : "+l"(d) : "l"(a), "l"(b));
}
__device__ __forceinline__ float2 unpack2(ull v) {
    float2 f; asm("mov.b64 {%0, %1}, %2;" : "=f"(f.x), "=f"(f.y) : "l"(v)); return f;
}
__device__ __forceinline__ ull d2l(double d) { return __double_as_longlong(d); }

__device__ __forceinline__ float fast_tanh(float x) {
    float y; asm("tanh.approx.f32 %0, %1;" : "=f"(y) : "f"(x)); return y;
}
__device__ __forceinline__ float fast_sigmoid(float x) {
    return 0.5f * fast_tanh(0.5f * x) + 0.5f;
}

// mma.sync m16n8k16 bf16 (baseline PTX, works on compute_103 — no 'a' features)
__device__ __forceinline__ void mma_bf16(float* d, const uint32_t* a, const uint32_t* b) {
    asm volatile(
        "mma.sync.aligned.m16n8k16.row.col.f32.bf16.bf16.f32 "
        "{%0,%1,%2,%3}, {%4,%5,%6,%7}, {%8,%9}, {%0,%1,%2,%3};"
        : "+f"(d[0]), "+f"(d[1]), "+f"(d[2]), "+f"(d[3])
        : "r"(a[0]), "r"(a[1]), "r"(a[2]), "r"(a[3]), "r"(b[0]), "r"(b[1]));
}

// ---------------------------------------------------------------------------
// init: zero h[0]
// ---------------------------------------------------------------------------
__global__ void init_kernel() {
    int i = blockIdx.x * blockDim.x + threadIdx.x;
    if (i < B * H) g_h[0][i] = 0.0f;
}

// ---------------------------------------------------------------------------
// prep_x: x fp32 -> bf16 hi/lo, same [m][k] layout
// ---------------------------------------------------------------------------
__global__ void __launch_bounds__(256) prep_x(const float* __restrict__ x) {
    size_t i = (size_t)blockIdx.x * blockDim.x + threadIdx.x;
    size_t o = i * 8;
    if (o >= (size_t)B * T * I) return;
    float4 v0 = *reinterpret_cast<const float4*>(x + o);
    float4 v1 = *reinterpret_cast<const float4*>(x + o + 4);
    __nv_bfloat16 hi[8], lo[8];
    #pragma unroll
    for (int j = 0; j < 8; ++j) {
        float f = (j < 4) ? (&v0.x)[j] : (&v1.x)[j - 4];
        __nv_bfloat16 h = __float2bfloat16(f);
        hi[j] = h;
        lo[j] = __float2bfloat16(f - __bfloat162float(h));
    }
    *reinterpret_cast<uint4*>(&g_xb_hi[o]) = *reinterpret_cast<uint4*>(hi);
    *reinterpret_cast<uint4*>(&g_xb_lo[o]) = *reinterpret_cast<uint4*>(lo);
}

// ---------------------------------------------------------------------------
// prep_w: transpose Wx [k][j] -> g_wb[fused n][k] bf16 hi/lo
// ---------------------------------------------------------------------------
__global__ void __launch_bounds__(256) prep_w(
    const float* __restrict__ w0, const float* __restrict__ w1,
    const float* __restrict__ w2, const float* __restrict__ w3)
{
    __shared__ float tl[32][33];
    const int gate = blockIdx.z;
    const int jt = blockIdx.x * 32;
    const int kt = blockIdx.y * 32;
    const float* __restrict__ w = (gate == 0) ? w0 : (gate == 1) ? w1 : (gate == 2) ? w2 : w3;
    const int tx = threadIdx.x, ty = threadIdx.y;
    #pragma unroll
    for (int r = 0; r < 4; ++r)
        tl[ty + r * 8][tx] = w[(size_t)(kt + ty + r * 8) * H + jt + tx];
    __syncthreads();
    #pragma unroll
    for (int r = 0; r < 4; ++r) {
        int j = jt + ty + r * 8;
        int k = kt + tx;
        float v = tl[tx][ty + r * 8];
        __nv_bfloat16 h = __float2bfloat16(v);
        size_t fc = (size_t)gate * H + j;
        g_wb_hi[fc * I + k] = h;
        g_wb_lo[fc * I + k] = __float2bfloat16(v - __bfloat162float(h));
    }
}

// ---------------------------------------------------------------------------
// xproj via mma.sync bf16, 3-pass hi/lo (hh + hl + lh), fp32 accum.
// CTA: 256 thr (8 warps, 2x4), tile M=128 x N=128, K=1024 in 16 x 64-k
// chunks staged in smem (single buffer, 2 CTAs/SM overlap).
// smem rows padded to 72 halves (36 words) -> conflict-free LDS.32 frags.
// ---------------------------------------------------------------------------
static constexpr int XROW = 72;                       // halves per smem row
static constexpr uint32_t XMAT = 128 * XROW * 2;      // 18432 B per matrix
static constexpr size_t SMEM_MMA = 4 * XMAT;          // 73728 B

__global__ void __launch_bounds__(256, 2) xproj_mma(
    const float* __restrict__ b0, const float* __restrict__ b1,
    const float* __restrict__ b2, const float* __restrict__ b3)
{
    extern __shared__ char sm[];
    __nv_bfloat16* sA_hi = reinterpret_cast<__nv_bfloat16*>(sm);
    __nv_bfloat16* sA_lo = reinterpret_cast<__nv_bfloat16*>(sm + XMAT);
    __nv_bfloat16* sB_hi = reinterpret_cast<__nv_bfloat16*>(sm + 2 * XMAT);
    __nv_bfloat16* sB_lo = reinterpret_cast<__nv_bfloat16*>(sm + 3 * XMAT);
    __shared__ float sbias[128];

    const int tid = threadIdx.x;
    const int wid = tid >> 5;
    const int lane = tid & 31;
    const int quad = lane >> 2;
    const int pr = lane & 3;
    const int mwarp = wid >> 2;          // 0..1 -> 64 rows
    const int nwarp = wid & 3;           // 0..3 -> 32 cols
    const int m0 = blockIdx.y * 128;
    const int n0 = blockIdx.x * 128;
    const int gate = n0 >> 10;
    const int j0f = n0 & (H - 1);
    const float* __restrict__ bias = (gate == 0) ? b0 : (gate == 1) ? b1
                                   : (gate == 2) ? b2 : b3;
    if (tid < 128) sbias[tid] = bias[j0f + tid];

    float acc[4][4][4];                  // [msub][nsub][frag]
    #pragma unroll
    for (int i = 0; i < 4; ++i)
        #pragma unroll
        for (int j = 0; j < 4; ++j)
            #pragma unroll
            for (int q = 0; q < 4; ++q) acc[i][j][q] = 0.0f;

    for (int c = 0; c < 16; ++c) {
        // ---- stage chunk c: 64 k-columns of A(hi,lo) and B(hi,lo) ----
        const size_t kb = (size_t)c * 64;
        #pragma unroll
        for (int i = 0; i < 4; ++i) {
            int g = tid + i * 256;       // 0..1023
            int row = g >> 3;
            int kg = g & 7;
            size_t asrc = (size_t)(m0 + row) * I + kb + kg * 8;
            size_t bsrc = (size_t)(n0 + row) * I + kb + kg * 8;
            uint4 vah = __ldcg(reinterpret_cast<const uint4*>(&g_xb_hi[asrc]));
            uint4 val = __ldcg(reinterpret_cast<const uint4*>(&g_xb_lo[asrc]));
            uint4 vbh = __ldcg(reinterpret_cast<const uint4*>(&g_wb_hi[bsrc]));
            uint4 vbl = __ldcg(reinterpret_cast<const uint4*>(&g_wb_lo[bsrc]));
            int d = row * XROW + kg * 8;
            *reinterpret_cast<uint4*>(&sA_hi[d]) = vah;
            *reinterpret_cast<uint4*>(&sA_lo[d]) = val;
            *reinterpret_cast<uint4*>(&sB_hi[d]) = vbh;
            *reinterpret_cast<uint4*>(&sB_lo[d]) = vbl;
        }
        __syncthreads();

        // ---- compute: 4 ksteps of 16 ----
        #pragma unroll
        for (int kk = 0; kk < 4; ++kk) {
            const int k0 = kk * 16;
            // B fragments for this warp's 4 n-subtiles (hi and lo)
            uint32_t bh[4][2], bl[4][2];
            #pragma unroll
            for (int ns = 0; ns < 4; ++ns) {
                int nrow = nwarp * 32 + ns * 8 + quad;
                int off = nrow * XROW + k0 + pr * 2;
                bh[ns][0] = *reinterpret_cast<const uint32_t*>(&sB_hi[off]);
                bh[ns][1] = *reinterpret_cast<const uint32_t*>(&sB_hi[off + 8]);
                bl[ns][0] = *reinterpret_cast<const uint32_t*>(&sB_lo[off]);
                bl[ns][1] = *reinterpret_cast<const uint32_t*>(&sB_lo[off + 8]);
            }
            #pragma unroll
            for (int ms = 0; ms < 4; ++ms) {
                int mrow = mwarp * 64 + ms * 16 + quad;
                int o0 = mrow * XROW + k0 + pr * 2;
                int o1 = (mrow + 8) * XROW + k0 + pr * 2;
                uint32_t ah[4], al[4];
                ah[0] = *reinterpret_cast<const uint32_t*>(&sA_hi[o0]);
                ah[1] = *reinterpret_cast<const uint32_t*>(&sA_hi[o1]);
                ah[2] = *reinterpret_cast<const uint32_t*>(&sA_hi[o0 + 8]);
                ah[3] = *reinterpret_cast<const uint32_t*>(&sA_hi[o1 + 8]);
                al[0] = *reinterpret_cast<const uint32_t*>(&sA_lo[o0]);
                al[1] = *reinterpret_cast<const uint32_t*>(&sA_lo[o1]);
                al[2] = *reinterpret_cast<const uint32_t*>(&sA_lo[o0 + 8]);
                al[3] = *reinterpret_cast<const uint32_t*>(&sA_lo[o1 + 8]);
                #pragma unroll
                for (int ns = 0; ns < 4; ++ns) {
                    mma_bf16(acc[ms][ns], ah, bh[ns]);   // hi*hi
                    mma_bf16(acc[ms][ns], ah, bl[ns]);   // hi*lo
                    mma_bf16(acc[ms][ns], al, bh[ns]);   // lo*hi
                }
            }
        }
        __syncthreads();
    }

    // ---- epilogue: add bias, scatter to g_xproj [t][b][4H] ----
    #pragma unroll
    for (int ms = 0; ms < 4; ++ms) {
        #pragma unroll
        for (int half = 0; half < 2; ++half) {
            int m = m0 + mwarp * 64 + ms * 16 + quad + half * 8;
            int t = m & (T - 1);
            int bb = m >> 9;
            size_t obase = ((size_t)t * B + bb) * G4H + n0;
            #pragma unroll
            for (int ns = 0; ns < 4; ++ns) {
                int ncol = nwarp * 32 + ns * 8 + pr * 2;
                float2 v;
                v.x = acc[ms][ns][half * 2 + 0] + sbias[ncol + 0];
                v.y = acc[ms][ns][half * 2 + 1] + sbias[ncol + 1];
                *reinterpret_cast<float2*>(&g_xproj[obase + ncol]) = v;
            }
        }
    }
}

// ---------------------------------------------------------------------------
// Persistent LSTM recurrence v3 (unchanged, 14.67ms-best).
// ---------------------------------------------------------------------------
static constexpr int KCH = 128;
static constexpr int NCH = H / KCH;
static constexpr int HROW = 132;
static constexpr int WS_FLOATS = H * 32;
static constexpr int HS_FLOATS = 2 * 64 * HROW;
static constexpr int GT_STRIDE = 36;
static constexpr int GT_FLOATS = 64 * GT_STRIDE;
static constexpr size_t SMEM_BYTES =
    (size_t)(WS_FLOATS + HS_FLOATS + GT_FLOATS) * 4;

__global__ void __launch_bounds__(NTHR, 1) lstm_persistent(
    const float* __restrict__ wh0, const float* __restrict__ wh1,
    const float* __restrict__ wh2, const float* __restrict__ wh3,
    float* __restrict__ out)
{
    extern __shared__ float smem[];
    float* ws = smem;
    float* hs = smem + WS_FLOATS;
    float* gt = smem + WS_FLOATS + HS_FLOATS;
    __shared__ unsigned s_sense;

    const int tid  = threadIdx.x;
    const int cg   = blockIdx.x;
    const int j0   = cg * 8;
    const int lane = tid & 31;
    const int wrp  = tid >> 5;
    const int fcq  = wrp & 3;
    const int kq   = wrp >> 2;

    for (int idx = tid; idx < 1024 * 8; idx += NTHR) {
        int kk = idx >> 3;
        int q = idx & 7;
        int gate = q >> 1;
        int jj4 = (q & 1) * 4;
        const float* __restrict__ wsel = (gate == 0) ? wh0 : (gate == 1) ? wh1
                                       : (gate == 2) ? wh2 : wh3;
        float4 v = *reinterpret_cast<const float4*>(&wsel[(size_t)kk * H + j0 + jj4]);
        *reinterpret_cast<float4*>(&ws[kk * 32 + q * 4]) = v;
    }
    if (tid == 0) s_sense = 0;
    __syncthreads();

    const int prow = tid >> 3;
    const int pjj = tid & 7;
    float creg = 0.0f;

    for (int t = 0; t < T; ++t) {
        const float* __restrict__ hin = g_h[t & 1];
        float* __restrict__ hout = g_h[(t + 1) & 1];

        float4 xpa[2], xpb[2];
        if (kq == 0) {
            #pragma unroll
            for (int rs = 0; rs < 2; ++rs) {
                int row = lane + rs * 32;
                size_t base = ((size_t)t * B + row) * G4H + (size_t)fcq * H + j0;
                xpa[rs] = *reinterpret_cast<const float4*>(&g_xproj[base]);
                xpb[rs] = *reinterpret_cast<const float4*>(&g_xproj[base + 4]);
            }
        }

        #pragma unroll
        for (int jld = 0; jld < 4; ++jld) {
            int idx = tid + 512 * jld;
            int row = idx >> 5;
            int k4 = idx & 31;
            float4 v = __ldcg(reinterpret_cast<const float4*>(&hin[row * H + k4 * 4]));
            *reinterpret_cast<float4*>(&hs[row * HROW + k4 * 4]) = v;
        }
        __syncthreads();

        ull acc[2][4];
        #pragma unroll
        for (int r = 0; r < 2; ++r)
            #pragma unroll
            for (int p = 0; p < 4; ++p) acc[r][p] = 0ULL;

        for (int c = 0; c < NCH; ++c) {
            float4 pf[4];
            if (c + 1 < NCH) {
                #pragma unroll
                for (int jld = 0; jld < 4; ++jld) {
                    int idx = tid + 512 * jld;
                    int row = idx >> 5;
                    int k4 = idx & 31;
                    pf[jld] = __ldcg(reinterpret_cast<const float4*>(
                        &hin[row * H + (c + 1) * KCH + k4 * 4]));
                }
            }

            const float* hb = hs + (c & 1) * (64 * HROW);
            const float* hap = hb + lane * HROW + kq * 32;
            const float* hbp = hb + (lane + 32) * HROW + kq * 32;
            const float* wsb = ws + (size_t)(c * KCH + kq * 32) * 32 + fcq * 8;

            #pragma unroll
            for (int k4 = 0; k4 < 8; ++k4) {
                float4 ha = *reinterpret_cast<const float4*>(hap + k4 * 4);
                float4 hbv = *reinterpret_cast<const float4*>(hbp + k4 * 4);
                const float* wk = wsb + k4 * 4 * 32;
                #pragma unroll
                for (int i = 0; i < 4; ++i) {
                    longlong2 w01 = *reinterpret_cast<const longlong2*>(wk + i * 32);
                    longlong2 w23 = *reinterpret_cast<const longlong2*>(wk + i * 32 + 4);
                    ull a0 = dup2((&ha.x)[i]);
                    ull a1 = dup2((&hbv.x)[i]);
                    fma2(acc[0][0], a0, (ull)w01.x);
                    fma2(acc[0][1], a0, (ull)w01.y);
                    fma2(acc[0][2], a0, (ull)w23.x);
                    fma2(acc[0][3], a0, (ull)w23.y);
                    fma2(acc[1][0], a1, (ull)w01.x);
                    fma2(acc[1][1], a1, (ull)w01.y);
                    fma2(acc[1][2], a1, (ull)w23.x);
                    fma2(acc[1][3], a1, (ull)w23.y);
                }
            }

            if (c + 1 < NCH) {
                float* hn = hs + ((c + 1) & 1) * (64 * HROW);
                #pragma unroll
                for (int jld = 0; jld < 4; ++jld) {
                    int idx = tid + 512 * jld;
                    int row = idx >> 5;
                    int k4 = idx & 31;
                    *reinterpret_cast<float4*>(&hn[row * HROW + k4 * 4]) = pf[jld];
                }
            }
            __syncthreads();
        }

        #pragma unroll
        for (int p = 0; p < 4; ++p) {
            if (kq == p) {
                #pragma unroll
                for (int rs = 0; rs < 2; ++rs) {
                    int row = lane + rs * 32;
                    float* g = gt + row * GT_STRIDE + fcq * 8;
                    float2 u0 = unpack2(acc[rs][0]);
                    float2 u1 = unpack2(acc[rs][1]);
                    float2 u2 = unpack2(acc[rs][2]);
                    float2 u3 = unpack2(acc[rs][3]);
                    if (p == 0) {
                        float4 va = make_float4(u0.x + xpa[rs].x, u0.y + xpa[rs].y,
                                                u1.x + xpa[rs].z, u1.y + xpa[rs].w);
                        float4 vb = make_float4(u2.x + xpb[rs].x, u2.y + xpb[rs].y,
                                                u3.x + xpb[rs].z, u3.y + xpb[rs].w);
                        *reinterpret_cast<float4*>(g) = va;
                        *reinterpret_cast<float4*>(g + 4) = vb;
                    } else {
                        float4 va = *reinterpret_cast<const float4*>(g);
                        float4 vb = *reinterpret_cast<const float4*>(g + 4);
                        va.x += u0.x; va.y += u0.y; va.z += u1.x; va.w += u1.y;
                        vb.x += u2.x; vb.y += u2.y; vb.z += u3.x; vb.w += u3.y;
                        *reinterpret_cast<float4*>(g) = va;
                        *reinterpret_cast<float4*>(g + 4) = vb;
                    }
                }
            }
            __syncthreads();
        }

        {
            float gi = gt[prow * GT_STRIDE + 0 + pjj];
            float gf = gt[prow * GT_STRIDE + 8 + pjj];
            float gg = gt[prow * GT_STRIDE + 16 + pjj];
            float go = gt[prow * GT_STRIDE + 24 + pjj];
            float ig = fast_sigmoid(gi);
            float fg = fast_sigmoid(gf);
            float gv = fast_tanh(gg);
            float og = fast_sigmoid(go);
            creg = fg * creg + ig * gv;
            float hv = og * fast_tanh(creg);
            int j = j0 + pjj;
            hout[prow * H + j] = hv;
            out[((size_t)prow * T + t) * H + j] = hv;
            if (t == T - 1) {
                size_t off = (size_t)B * T * H;
                out[off + (size_t)prow * H + j] = hv;
                out[off + (size_t)B * H + (size_t)prow * H + j] = creg;
            }
        }

        __syncthreads();
        if (tid == 0) {
            __threadfence();
            unsigned s = s_sense ^ 1u;
            s_sense = s;
            if (atomicAdd(&g_bar_count, 1u) == NCTA - 1u) {
                g_bar_count = 0;
                asm volatile("st.release.gpu.global.u32 [%0], %1;"
                             :: "l"(&g_bar_sense), "r"(s) : "memory");
            } else {
                unsigned v;
                while (true) {
                    asm volatile("ld.acquire.gpu.global.u32 %0, [%1];"
                                 : "=r"(v) : "l"(&g_bar_sense) : "memory");
                    if (v == s) break;
                    __nanosleep(32);
                }
            }
        }
        __syncthreads();
    }
}

// ---------------------------------------------------------------------------
extern "C" void kernel_launch(void* const* d_in, const int* in_sizes, int n_in,
                              void* d_out, int out_size)
{
    const float* x   = (const float*)d_in[0];
    const float* wii = (const float*)d_in[1];
    const float* whi = (const float*)d_in[2];
    const float* bi  = (const float*)d_in[3];
    const float* wif = (const float*)d_in[4];
    const float* whf = (const float*)d_in[5];
    const float* bf  = (const float*)d_in[6];
    const float* wig = (const float*)d_in[7];
    const float* whg = (const float*)d_in[8];
    const float* bg  = (const float*)d_in[9];
    const float* wio = (const float*)d_in[10];
    const float* who = (const float*)d_in[11];
    const float* bo  = (const float*)d_in[12];
    float* out = (float*)d_out;

    cudaFuncSetAttribute(lstm_persistent,
                         cudaFuncAttributeMaxDynamicSharedMemorySize,
                         (int)SMEM_BYTES);
    cudaFuncSetAttribute(xproj_mma,
                         cudaFuncAttributeMaxDynamicSharedMemorySize,
                         (int)SMEM_MMA);

    init_kernel<<<(B * H + 255) / 256, 256>>>();

    // bf16 hi/lo operand prep
    prep_x<<<16384, 256>>>(x);
    {
        dim3 g(32, 32, 4), blk(32, 8);
        prep_w<<<g, blk>>>(wii, wif, wig, wio);
    }

    // tensor-core xproj (mma.sync)
    {
        dim3 g(G4H / 128, (B * T) / 128);   // (32, 256)
        xproj_mma<<<g, 256, SMEM_MMA>>>(bi, bf, bg, bo);
    }

    lstm_persistent<<<NCTA, NTHR, SMEM_BYTES>>>(whi, whf, whg, who, out);
}

// round 13
// speedup vs baseline: 1.9346x; 1.4494x over previous
#include <cuda_runtime.h>
#include <cuda_bf16.h>
#include <math.h>
#include <stdint.h>

typedef unsigned long long ull;

// Problem constants
static constexpr int B = 64;
static constexpr int T = 512;
static constexpr int I = 1024;
static constexpr int H = 1024;
static constexpr int G4H = 4 * H;   // 4096

static constexpr int NCTA = 128;

// Scratch in device globals (no allocation allowed)
__device__ float g_xproj[(size_t)T * B * G4H];  // [T][B][4H]
__device__ __nv_bfloat16 g_hbf[2][2][B][H];     // [pingpong][hi/lo][row][k]
__device__ unsigned g_bar_count = 0;
__device__ unsigned g_bar_sense = 0;

// bf16 hi/lo operands for the tensor-core xproj GEMM
__device__ __nv_bfloat16 g_xb_hi[(size_t)B * T * I];   // [m][k]
__device__ __nv_bfloat16 g_xb_lo[(size_t)B * T * I];
__device__ __nv_bfloat16 g_wb_hi[(size_t)G4H * I];     // [fused n][k]  (W^T)
__device__ __nv_bfloat16 g_wb_lo[(size_t)G4H * I];

// ---------------------------------------------------------------------------
// helpers
// ---------------------------------------------------------------------------
__device__ __forceinline__ float fast_tanh(float x) {
    float y; asm("tanh.approx.f32 %0, %1;" : "=f"(y) : "f"(x)); return y;
}
__device__ __forceinline__ float fast_sigmoid(float x) {
    return 0.5f * fast_tanh(0.5f * x) + 0.5f;
}

// mma.sync m16n8k16 bf16 (baseline PTX — compiles for compute_103)
__device__ __forceinline__ void mma_bf16(float* d, const uint32_t* a, const uint32_t* b) {
    asm volatile(
        "mma.sync.aligned.m16n8k16.row.col.f32.bf16.bf16.f32 "
        "{%0,%1,%2,%3}, {%4,%5,%6,%7}, {%8,%9}, {%0,%1,%2,%3};"
        : "+f"(d[0]), "+f"(d[1]), "+f"(d[2]), "+f"(d[3])
        : "r"(a[0]), "r"(a[1]), "r"(a[2]), "r"(a[3]), "r"(b[0]), "r"(b[1]));
}

// ---------------------------------------------------------------------------
// init: zero h[0] (bf16 hi/lo)
// ---------------------------------------------------------------------------
__global__ void init_kernel() {
    int i = blockIdx.x * blockDim.x + threadIdx.x;
    if (i < 16384)   // 2*64*1024 bf16 = 16384 uint4
        reinterpret_cast<uint4*>(&g_hbf[0][0][0][0])[i] = make_uint4(0, 0, 0, 0);
}

// ---------------------------------------------------------------------------
// prep_x: x fp32 -> bf16 hi/lo, same [m][k] layout
// ---------------------------------------------------------------------------
__global__ void __launch_bounds__(256) prep_x(const float* __restrict__ x) {
    size_t i = (size_t)blockIdx.x * blockDim.x + threadIdx.x;
    size_t o = i * 8;
    if (o >= (size_t)B * T * I) return;
    float4 v0 = *reinterpret_cast<const float4*>(x + o);
    float4 v1 = *reinterpret_cast<const float4*>(x + o + 4);
    __nv_bfloat16 hi[8], lo[8];
    #pragma unroll
    for (int j = 0; j < 8; ++j) {
        float f = (j < 4) ? (&v0.x)[j] : (&v1.x)[j - 4];
        __nv_bfloat16 h = __float2bfloat16(f);
        hi[j] = h;
        lo[j] = __float2bfloat16(f - __bfloat162float(h));
    }
    *reinterpret_cast<uint4*>(&g_xb_hi[o]) = *reinterpret_cast<uint4*>(hi);
    *reinterpret_cast<uint4*>(&g_xb_lo[o]) = *reinterpret_cast<uint4*>(lo);
}

// ---------------------------------------------------------------------------
// prep_w: transpose Wx [k][j] -> g_wb[fused n][k] bf16 hi/lo
// ---------------------------------------------------------------------------
__global__ void __launch_bounds__(256) prep_w(
    const float* __restrict__ w0, const float* __restrict__ w1,
    const float* __restrict__ w2, const float* __restrict__ w3)
{
    __shared__ float tl[32][33];
    const int gate = blockIdx.z;
    const int jt = blockIdx.x * 32;
    const int kt = blockIdx.y * 32;
    const float* __restrict__ w = (gate == 0) ? w0 : (gate == 1) ? w1 : (gate == 2) ? w2 : w3;
    const int tx = threadIdx.x, ty = threadIdx.y;
    #pragma unroll
    for (int r = 0; r < 4; ++r)
        tl[ty + r * 8][tx] = w[(size_t)(kt + ty + r * 8) * H + jt + tx];
    __syncthreads();
    #pragma unroll
    for (int r = 0; r < 4; ++r) {
        int j = jt + ty + r * 8;
        int k = kt + tx;
        float v = tl[tx][ty + r * 8];
        __nv_bfloat16 h = __float2bfloat16(v);
        size_t fc = (size_t)gate * H + j;
        g_wb_hi[fc * I + k] = h;
        g_wb_lo[fc * I + k] = __float2bfloat16(v - __bfloat162float(h));
    }
}

// ---------------------------------------------------------------------------
// xproj via mma.sync (unchanged from R12, 68.9% tensor)
// ---------------------------------------------------------------------------
static constexpr int XROW = 72;
static constexpr uint32_t XMAT = 128 * XROW * 2;
static constexpr size_t SMEM_MMA = 4 * XMAT;

__global__ void __launch_bounds__(256, 2) xproj_mma(
    const float* __restrict__ b0, const float* __restrict__ b1,
    const float* __restrict__ b2, const float* __restrict__ b3)
{
    extern __shared__ char sm[];
    __nv_bfloat16* sA_hi = reinterpret_cast<__nv_bfloat16*>(sm);
    __nv_bfloat16* sA_lo = reinterpret_cast<__nv_bfloat16*>(sm + XMAT);
    __nv_bfloat16* sB_hi = reinterpret_cast<__nv_bfloat16*>(sm + 2 * XMAT);
    __nv_bfloat16* sB_lo = reinterpret_cast<__nv_bfloat16*>(sm + 3 * XMAT);
    __shared__ float sbias[128];

    const int tid = threadIdx.x;
    const int wid = tid >> 5;
    const int lane = tid & 31;
    const int quad = lane >> 2;
    const int pr = lane & 3;
    const int mwarp = wid >> 2;
    const int nwarp = wid & 3;
    const int m0 = blockIdx.y * 128;
    const int n0 = blockIdx.x * 128;
    const int gate = n0 >> 10;
    const int j0f = n0 & (H - 1);
    const float* __restrict__ bias = (gate == 0) ? b0 : (gate == 1) ? b1
                                   : (gate == 2) ? b2 : b3;
    if (tid < 128) sbias[tid] = bias[j0f + tid];

    float acc[4][4][4];
    #pragma unroll
    for (int i = 0; i < 4; ++i)
        #pragma unroll
        for (int j = 0; j < 4; ++j)
            #pragma unroll
            for (int q = 0; q < 4; ++q) acc[i][j][q] = 0.0f;

    for (int c = 0; c < 16; ++c) {
        const size_t kb = (size_t)c * 64;
        #pragma unroll
        for (int i = 0; i < 4; ++i) {
            int g = tid + i * 256;
            int row = g >> 3;
            int kg = g & 7;
            size_t asrc = (size_t)(m0 + row) * I + kb + kg * 8;
            size_t bsrc = (size_t)(n0 + row) * I + kb + kg * 8;
            uint4 vah = __ldcg(reinterpret_cast<const uint4*>(&g_xb_hi[asrc]));
            uint4 val = __ldcg(reinterpret_cast<const uint4*>(&g_xb_lo[asrc]));
            uint4 vbh = __ldcg(reinterpret_cast<const uint4*>(&g_wb_hi[bsrc]));
            uint4 vbl = __ldcg(reinterpret_cast<const uint4*>(&g_wb_lo[bsrc]));
            int d = row * XROW + kg * 8;
            *reinterpret_cast<uint4*>(&sA_hi[d]) = vah;
            *reinterpret_cast<uint4*>(&sA_lo[d]) = val;
            *reinterpret_cast<uint4*>(&sB_hi[d]) = vbh;
            *reinterpret_cast<uint4*>(&sB_lo[d]) = vbl;
        }
        __syncthreads();

        #pragma unroll
        for (int kk = 0; kk < 4; ++kk) {
            const int k0 = kk * 16;
            uint32_t bh[4][2], bl[4][2];
            #pragma unroll
            for (int ns = 0; ns < 4; ++ns) {
                int nrow = nwarp * 32 + ns * 8 + quad;
                int off = nrow * XROW + k0 + pr * 2;
                bh[ns][0] = *reinterpret_cast<const uint32_t*>(&sB_hi[off]);
                bh[ns][1] = *reinterpret_cast<const uint32_t*>(&sB_hi[off + 8]);
                bl[ns][0] = *reinterpret_cast<const uint32_t*>(&sB_lo[off]);
                bl[ns][1] = *reinterpret_cast<const uint32_t*>(&sB_lo[off + 8]);
            }
            #pragma unroll
            for (int ms = 0; ms < 4; ++ms) {
                int mrow = mwarp * 64 + ms * 16 + quad;
                int o0 = mrow * XROW + k0 + pr * 2;
                int o1 = (mrow + 8) * XROW + k0 + pr * 2;
                uint32_t ah[4], al[4];
                ah[0] = *reinterpret_cast<const uint32_t*>(&sA_hi[o0]);
                ah[1] = *reinterpret_cast<const uint32_t*>(&sA_hi[o1]);
                ah[2] = *reinterpret_cast<const uint32_t*>(&sA_hi[o0 + 8]);
                ah[3] = *reinterpret_cast<const uint32_t*>(&sA_hi[o1 + 8]);
                al[0] = *reinterpret_cast<const uint32_t*>(&sA_lo[o0]);
                al[1] = *reinterpret_cast<const uint32_t*>(&sA_lo[o1]);
                al[2] = *reinterpret_cast<const uint32_t*>(&sA_lo[o0 + 8]);
                al[3] = *reinterpret_cast<const uint32_t*>(&sA_lo[o1 + 8]);
                #pragma unroll
                for (int ns = 0; ns < 4; ++ns) {
                    mma_bf16(acc[ms][ns], ah, bh[ns]);
                    mma_bf16(acc[ms][ns], ah, bl[ns]);
                    mma_bf16(acc[ms][ns], al, bh[ns]);
                }
            }
        }
        __syncthreads();
    }

    #pragma unroll
    for (int ms = 0; ms < 4; ++ms) {
        #pragma unroll
        for (int half = 0; half < 2; ++half) {
            int m = m0 + mwarp * 64 + ms * 16 + quad + half * 8;
            int t = m & (T - 1);
            int bb = m >> 9;
            size_t obase = ((size_t)t * B + bb) * G4H + n0;
            #pragma unroll
            for (int ns = 0; ns < 4; ++ns) {
                int ncol = nwarp * 32 + ns * 8 + pr * 2;
                float2 v;
                v.x = acc[ms][ns][half * 2 + 0] + sbias[ncol + 0];
                v.y = acc[ms][ns][half * 2 + 1] + sbias[ncol + 1];
                *reinterpret_cast<float2*>(&g_xproj[obase + ncol]) = v;
            }
        }
    }
}

// ---------------------------------------------------------------------------
// Persistent LSTM recurrence v4 — mma.sync tensor cores.
//
// 128 CTAs x 512 threads (16 warps), 1 CTA/SM. CTA cg owns 32 fused cols
// (fc = gate*8+jj -> H-col cg*8+jj), all 64 rows, all T steps.
// Per step: gates[64x32] = h[64x1024] @ Wh^T, 3-pass bf16 hi/lo
// (hh + hl + lh), fp32 accum, via m16n8k16.
//
// Warp map: nh = wrp&1 (16 cols = 2 n-tiles), kq = wrp>>1 (k-step within
// each 128-k chunk). Per chunk per warp: 1 kstep x 2 ntiles x 4 mtiles x 3
// passes = 24 mmas. B-frags (weights) read from resident smem, reused
// across 4 m-tiles. 8-way k-split reduced via two gt copies in 4 passes.
//
// SMEM: wsb hi/lo [32 fc][1024 k] bf16 (pad 1032)   132,096 B  (resident)
//       hs [2 buf][hi/lo][64 rows][128 k] (pad 136)  69,632 B
//       gt0, gt1 [64][36] f32                        18,432 B   -> 220,160 B
// ---------------------------------------------------------------------------
static constexpr int RWS = 1032;                    // wsb row stride (halfs)
static constexpr int RHS = 136;                     // hs row stride (halfs)
static constexpr size_t WSB_HI = 0;
static constexpr size_t WSB_LO = 32 * RWS * 2;               // 66048
static constexpr size_t HS_OFF = 2 * 32 * RWS * 2;           // 132096
static constexpr size_t HS_MAT = 64 * RHS * 2;               // 17408
// order: buf0_hi, buf0_lo, buf1_hi, buf1_lo
static constexpr size_t GT0_OFF = HS_OFF + 4 * HS_MAT;       // 201728
static constexpr int GTS = 36;
static constexpr size_t GT1_OFF = GT0_OFF + 64 * GTS * 4;
static constexpr size_t SMEM_REC = GT1_OFF + 64 * GTS * 4;   // 220160

__global__ void __launch_bounds__(512, 1) lstm_rec_mma(
    const float* __restrict__ wh0, const float* __restrict__ wh1,
    const float* __restrict__ wh2, const float* __restrict__ wh3,
    float* __restrict__ out)
{
    extern __shared__ char sm[];
    __nv_bfloat16* wsb_hi = reinterpret_cast<__nv_bfloat16*>(sm + WSB_HI);
    __nv_bfloat16* wsb_lo = reinterpret_cast<__nv_bfloat16*>(sm + WSB_LO);
    float* gt0 = reinterpret_cast<float*>(sm + GT0_OFF);
    float* gt1 = reinterpret_cast<float*>(sm + GT1_OFF);
    __shared__ unsigned s_sense;

    const int tid = threadIdx.x;
    const int cg = blockIdx.x;
    const int j0 = cg * 8;
    const int lane = tid & 31;
    const int wrp = tid >> 5;
    const int quad = lane >> 2;
    const int pr = lane & 3;
    const int nh = wrp & 1;
    const int kq = wrp >> 1;

    // ---- build resident Wh hi/lo in B-frag row layout [fc][k], once ----
    for (int idx = tid; idx < 32 * 1024; idx += 512) {
        int fc = idx & 31;
        int k = idx >> 5;
        int gate = fc >> 3, jj = fc & 7;
        const float* __restrict__ wsel = (gate == 0) ? wh0 : (gate == 1) ? wh1
                                       : (gate == 2) ? wh2 : wh3;
        float w = wsel[(size_t)k * H + j0 + jj];
        __nv_bfloat16 h = __float2bfloat16(w);
        wsb_hi[fc * RWS + k] = h;
        wsb_lo[fc * RWS + k] = __float2bfloat16(w - __bfloat162float(h));
    }
    if (tid == 0) s_sense = 0;
    __syncthreads();

    // pointwise ownership: one (row, jj) per thread
    const int prow = tid >> 3;
    const int pjj = tid & 7;
    float creg = 0.0f;

    // staging map: idx = tid + 512*j -> row = idx>>4, grp = idx&15 (8 halfs)
    const int srow = tid >> 4;
    const int sgrp = tid & 15;

    for (int t = 0; t < T; ++t) {
        const __nv_bfloat16* hin_hi = &g_hbf[t & 1][0][0][0];
        const __nv_bfloat16* hin_lo = &g_hbf[t & 1][1][0][0];

        // xproj prefetch for the pointwise
        float xp[4];
        {
            size_t xb = ((size_t)t * B + prow) * G4H + j0 + pjj;
            #pragma unroll
            for (int g = 0; g < 4; ++g)
                xp[g] = __ldcg(&g_xproj[xb + (size_t)g * H]);
        }

        // stage chunk 0
        {
            char* d_hi = sm + HS_OFF;
            char* d_lo = sm + HS_OFF + HS_MAT;
            #pragma unroll
            for (int j = 0; j < 2; ++j) {
                int r = srow + j * 32;
                size_t src = (size_t)r * H + sgrp * 8;
                uint4 vh = __ldcg(reinterpret_cast<const uint4*>(hin_hi + src));
                uint4 vl = __ldcg(reinterpret_cast<const uint4*>(hin_lo + src));
                int d = (r * RHS + sgrp * 8) * 2;
                *reinterpret_cast<uint4*>(d_hi + d) = vh;
                *reinterpret_cast<uint4*>(d_lo + d) = vl;
            }
        }
        __syncthreads();

        float acc[4][2][4];
        #pragma unroll
        for (int mt = 0; mt < 4; ++mt)
            #pragma unroll
            for (int nt = 0; nt < 2; ++nt)
                #pragma unroll
                for (int q = 0; q < 4; ++q) acc[mt][nt][q] = 0.0f;

        for (int c = 0; c < 8; ++c) {
            const int b = c & 1;
            // register-prefetch chunk c+1
            uint4 pfh[2], pfl[2];
            if (c + 1 < 8) {
                #pragma unroll
                for (int j = 0; j < 2; ++j) {
                    int r = srow + j * 32;
                    size_t src = (size_t)r * H + (c + 1) * 128 + sgrp * 8;
                    pfh[j] = __ldcg(reinterpret_cast<const uint4*>(hin_hi + src));
                    pfl[j] = __ldcg(reinterpret_cast<const uint4*>(hin_lo + src));
                }
            }

            // ---- compute: warp kq handles kstep kq of this chunk ----
            const __nv_bfloat16* hs_hi = reinterpret_cast<const __nv_bfloat16*>(
                sm + HS_OFF + (b * 2) * HS_MAT);
            const __nv_bfloat16* hs_lo = reinterpret_cast<const __nv_bfloat16*>(
                sm + HS_OFF + (b * 2 + 1) * HS_MAT);
            const int kglob = c * 128 + kq * 16;
            const int klocal = kq * 16;

            uint32_t Bh[2][2], Bl[2][2];
            #pragma unroll
            for (int nt = 0; nt < 2; ++nt) {
                int fr = nh * 16 + nt * 8 + quad;
                const __nv_bfloat16* ph = wsb_hi + fr * RWS + kglob + pr * 2;
                const __nv_bfloat16* pl = wsb_lo + fr * RWS + kglob + pr * 2;
                Bh[nt][0] = *reinterpret_cast<const uint32_t*>(ph);
                Bh[nt][1] = *reinterpret_cast<const uint32_t*>(ph + 8);
                Bl[nt][0] = *reinterpret_cast<const uint32_t*>(pl);
                Bl[nt][1] = *reinterpret_cast<const uint32_t*>(pl + 8);
            }
            #pragma unroll
            for (int mt = 0; mt < 4; ++mt) {
                int ar = mt * 16 + quad;
                const __nv_bfloat16* pa0 = hs_hi + ar * RHS + klocal + pr * 2;
                const __nv_bfloat16* pa1 = hs_hi + (ar + 8) * RHS + klocal + pr * 2;
                const __nv_bfloat16* pb0 = hs_lo + ar * RHS + klocal + pr * 2;
                const __nv_bfloat16* pb1 = hs_lo + (ar + 8) * RHS + klocal + pr * 2;
                uint32_t Ah[4], Al[4];
                Ah[0] = *reinterpret_cast<const uint32_t*>(pa0);
                Ah[1] = *reinterpret_cast<const uint32_t*>(pa1);
                Ah[2] = *reinterpret_cast<const uint32_t*>(pa0 + 8);
                Ah[3] = *reinterpret_cast<const uint32_t*>(pa1 + 8);
                Al[0] = *reinterpret_cast<const uint32_t*>(pb0);
                Al[1] = *reinterpret_cast<const uint32_t*>(pb1);
                Al[2] = *reinterpret_cast<const uint32_t*>(pb0 + 8);
                Al[3] = *reinterpret_cast<const uint32_t*>(pb1 + 8);
                #pragma unroll
                for (int nt = 0; nt < 2; ++nt) {
                    mma_bf16(acc[mt][nt], Ah, Bh[nt]);   // hi*hi
                    mma_bf16(acc[mt][nt], Ah, Bl[nt]);   // hi*lo
                    mma_bf16(acc[mt][nt], Al, Bh[nt]);   // lo*hi
                }
            }

            // commit prefetched chunk into the other buffer
            if (c + 1 < 8) {
                char* d_hi = sm + HS_OFF + (((c + 1) & 1) * 2) * HS_MAT;
                char* d_lo = d_hi + HS_MAT;
                #pragma unroll
                for (int j = 0; j < 2; ++j) {
                    int r = srow + j * 32;
                    int d = (r * RHS + sgrp * 8) * 2;
                    *reinterpret_cast<uint4*>(d_hi + d) = pfh[j];
                    *reinterpret_cast<uint4*>(d_lo + d) = pfl[j];
                }
            }
            __syncthreads();
        }

        // ---- 8-way k-split reduction: pairs (2p -> gt0, 2p+1 -> gt1) ----
        #pragma unroll
        for (int p = 0; p < 4; ++p) {
            if ((kq >> 1) == p) {
                float* g = (kq & 1) ? gt1 : gt0;
                #pragma unroll
                for (int mt = 0; mt < 4; ++mt)
                    #pragma unroll
                    for (int half = 0; half < 2; ++half) {
                        int row = mt * 16 + quad + half * 8;
                        #pragma unroll
                        for (int nt = 0; nt < 2; ++nt) {
                            int col = nh * 16 + nt * 8 + pr * 2;
                            float2 v;
                            v.x = acc[mt][nt][half * 2 + 0];
                            v.y = acc[mt][nt][half * 2 + 1];
                            float* gp = g + row * GTS + col;
                            if (p == 0) {
                                *reinterpret_cast<float2*>(gp) = v;
                            } else {
                                float2 o = *reinterpret_cast<const float2*>(gp);
                                o.x += v.x; o.y += v.y;
                                *reinterpret_cast<float2*>(gp) = o;
                            }
                        }
                    }
            }
            __syncthreads();
        }

        // ---- pointwise LSTM cell ----
        {
            float gv4[4];
            #pragma unroll
            for (int g = 0; g < 4; ++g) {
                int fc = g * 8 + pjj;
                gv4[g] = gt0[prow * GTS + fc] + gt1[prow * GTS + fc] + xp[g];
            }
            float ig = fast_sigmoid(gv4[0]);
            float fg = fast_sigmoid(gv4[1]);
            float gg = fast_tanh(gv4[2]);
            float og = fast_sigmoid(gv4[3]);
            creg = fg * creg + ig * gg;
            float hv = og * fast_tanh(creg);
            int j = j0 + pjj;
            const int nb = (t + 1) & 1;
            __nv_bfloat16 hh = __float2bfloat16(hv);
            g_hbf[nb][0][prow][j] = hh;
            g_hbf[nb][1][prow][j] = __float2bfloat16(hv - __bfloat162float(hh));
            out[((size_t)prow * T + t) * H + j] = hv;
            if (t == T - 1) {
                size_t off = (size_t)B * T * H;
                out[off + (size_t)prow * H + j] = hv;
                out[off + (size_t)B * H + (size_t)prow * H + j] = creg;
            }
        }

        // ---- grid barrier ----
        __syncthreads();
        if (tid == 0) {
            __threadfence();
            unsigned s = s_sense ^ 1u;
            s_sense = s;
            if (atomicAdd(&g_bar_count, 1u) == NCTA - 1u) {
                g_bar_count = 0;
                asm volatile("st.release.gpu.global.u32 [%0], %1;"
                             :: "l"(&g_bar_sense), "r"(s) : "memory");
            } else {
                unsigned v;
                while (true) {
                    asm volatile("ld.acquire.gpu.global.u32 %0, [%1];"
                                 : "=r"(v) : "l"(&g_bar_sense) : "memory");
                    if (v == s) break;
                    __nanosleep(32);
                }
            }
        }
        __syncthreads();
    }
}

// ---------------------------------------------------------------------------
extern "C" void kernel_launch(void* const* d_in, const int* in_sizes, int n_in,
                              void* d_out, int out_size)
{
    const float* x   = (const float*)d_in[0];
    const float* wii = (const float*)d_in[1];
    const float* whi = (const float*)d_in[2];
    const float* bi  = (const float*)d_in[3];
    const float* wif = (const float*)d_in[4];
    const float* whf = (const float*)d_in[5];
    const float* bf  = (const float*)d_in[6];
    const float* wig = (const float*)d_in[7];
    const float* whg = (const float*)d_in[8];
    const float* bg  = (const float*)d_in[9];
    const float* wio = (const float*)d_in[10];
    const float* who = (const float*)d_in[11];
    const float* bo  = (const float*)d_in[12];
    float* out = (float*)d_out;

    cudaFuncSetAttribute(xproj_mma,
                         cudaFuncAttributeMaxDynamicSharedMemorySize,
                         (int)SMEM_MMA);
    cudaFuncSetAttribute(lstm_rec_mma,
                         cudaFuncAttributeMaxDynamicSharedMemorySize,
                         (int)SMEM_REC);

    init_kernel<<<64, 256>>>();

    // bf16 hi/lo operand prep
    prep_x<<<16384, 256>>>(x);
    {
        dim3 g(32, 32, 4), blk(32, 8);
        prep_w<<<g, blk>>>(wii, wif, wig, wio);
    }

    // tensor-core xproj
    {
        dim3 g(G4H / 128, (B * T) / 128);   // (32, 256)
        xproj_mma<<<g, 256, SMEM_MMA>>>(bi, bf, bg, bo);
    }

    // tensor-core persistent recurrence
    lstm_rec_mma<<<NCTA, 512, SMEM_REC>>>(whi, whf, whg, who, out);
}